// round 2
// baseline (speedup 1.0000x reference)
#include <cuda_runtime.h>
#include <math.h>

#define NN 20000
#define EE 80000
#define DD 128
#define HH 4
#define HD 512          // H*D

// ---------------- scratch (device globals; no allocations allowed) ----------------
__device__ float g_XL[NN * HD];
__device__ float g_XR[NN * HD];
__device__ float g_Fd[NN * DD];
__device__ float g_Fs[NN * DD];
__device__ float g_Sd[NN * DD];
__device__ float g_Ss[NN * DD];
__device__ float g_alpha[EE * HH];
__device__ float g_tmp_my[NN * DD];
__device__ float g_tmp_opp[NN * DD];
__device__ float g_xmy[NN * DD];
__device__ float g_xopp[NN * DD];
__device__ int   g_indptr[4 * (NN + 1)];
__device__ int   g_cnt[4 * NN];
__device__ int   g_cursor[4 * NN];
__device__ int   g_srcs[4 * EE];
__device__ int   g_dsts[4 * EE];

// ---------------- helpers ----------------
__device__ __forceinline__ float sigmoidf_(float x) { return 1.0f / (1.0f + expf(-x)); }
__device__ __forceinline__ float softplusf_(float x) {
    // = logaddexp(x, 0), numerically stable, matches jax.nn.softplus
    return fmaxf(x, 0.0f) + log1pf(expf(-fabsf(x)));
}

// ---------------- CSR build ----------------
__global__ void count_k(const int* __restrict__ dst, int* __restrict__ cnt) {
    int e = blockIdx.x * blockDim.x + threadIdx.x;
    if (e < EE) atomicAdd(&cnt[dst[e]], 1);
}

__global__ void exscan_k(const int* __restrict__ cnt, int* __restrict__ indptr) {
    __shared__ int buf[1024];
    __shared__ int carry;
    int t = threadIdx.x;
    if (t == 0) { carry = 0; indptr[0] = 0; }
    __syncthreads();
    for (int base = 0; base < NN; base += 1024) {
        int i = base + t;
        int v = (i < NN) ? cnt[i] : 0;
        buf[t] = v;
        __syncthreads();
        for (int off = 1; off < 1024; off <<= 1) {
            int tv = (t >= off) ? buf[t - off] : 0;
            __syncthreads();
            buf[t] += tv;
            __syncthreads();
        }
        if (i < NN) indptr[i + 1] = carry + buf[t];
        __syncthreads();
        if (t == 0) carry += buf[1023];
        __syncthreads();
    }
}

__global__ void scatter_k(const int* __restrict__ src, const int* __restrict__ dst,
                          int* __restrict__ cursor, int* __restrict__ srcs,
                          int* __restrict__ dsts) {
    int e = blockIdx.x * blockDim.x + threadIdx.x;
    if (e >= EE) return;
    int d = dst[e];
    int p = atomicAdd(&cursor[d], 1);
    srcs[p] = src[e];
    dsts[p] = d;
}

// ---------------- fp32 SGEMM: C[M,Ncols] = A[M,128] @ B[128,Ncols] (+bias) ------------
// Tile 128x128, BK=16, 256 threads, 8x8 per thread.
__global__ __launch_bounds__(256) void sgemm128(const float* __restrict__ A,
                                                const float* __restrict__ B,
                                                const float* __restrict__ bias,
                                                float* __restrict__ C,
                                                int M, int Ncols) {
    __shared__ float As[16][128];
    __shared__ float Bs[16][128];
    const int brow = blockIdx.y * 128;
    const int bcol = blockIdx.x * 128;
    const int tid = threadIdx.x;
    const int tx = tid & 15;   // 0..15 -> cols
    const int ty = tid >> 4;   // 0..15 -> rows

    float acc[8][8];
#pragma unroll
    for (int i = 0; i < 8; i++)
#pragma unroll
        for (int j = 0; j < 8; j++) acc[i][j] = 0.0f;

    for (int k0 = 0; k0 < 128; k0 += 16) {
#pragma unroll
        for (int i = 0; i < 2; i++) {
            int idx = tid + i * 256;     // 0..511
            int r = idx >> 2;            // 0..127
            int c4 = (idx & 3) * 4;      // 0,4,8,12
            float4 v = make_float4(0.f, 0.f, 0.f, 0.f);
            int gr = brow + r;
            if (gr < M) v = *(const float4*)&A[(size_t)gr * 128 + k0 + c4];
            As[c4 + 0][r] = v.x;
            As[c4 + 1][r] = v.y;
            As[c4 + 2][r] = v.z;
            As[c4 + 3][r] = v.w;
        }
#pragma unroll
        for (int i = 0; i < 2; i++) {
            int idx = tid + i * 256;
            int r = idx >> 5;            // 0..15
            int c4 = (idx & 31) * 4;     // 0..124
            float4 v = *(const float4*)&B[(size_t)(k0 + r) * Ncols + bcol + c4];
            *(float4*)&Bs[r][c4] = v;
        }
        __syncthreads();
#pragma unroll
        for (int kk = 0; kk < 16; kk++) {
            float a[8], b[8];
            float4 a0 = *(const float4*)&As[kk][ty * 8];
            float4 a1 = *(const float4*)&As[kk][ty * 8 + 4];
            float4 b0 = *(const float4*)&Bs[kk][tx * 8];
            float4 b1 = *(const float4*)&Bs[kk][tx * 8 + 4];
            a[0] = a0.x; a[1] = a0.y; a[2] = a0.z; a[3] = a0.w;
            a[4] = a1.x; a[5] = a1.y; a[6] = a1.z; a[7] = a1.w;
            b[0] = b0.x; b[1] = b0.y; b[2] = b0.z; b[3] = b0.w;
            b[4] = b1.x; b[5] = b1.y; b[6] = b1.z; b[7] = b1.w;
#pragma unroll
            for (int i = 0; i < 8; i++)
#pragma unroll
                for (int j = 0; j < 8; j++) acc[i][j] += a[i] * b[j];
        }
        __syncthreads();
    }

#pragma unroll
    for (int i = 0; i < 8; i++) {
        int gr = brow + ty * 8 + i;
        if (gr < M) {
#pragma unroll
            for (int j = 0; j < 8; j++) {
                int gc = bcol + tx * 8 + j;
                float v = acc[i][j];
                if (bias) v += bias[gc];
                C[(size_t)gr * Ncols + gc] = v;
            }
        }
    }
}

// ---------------- GATv2 edge score: one warp per edge (grid-stride) ----------------
__global__ void gat_score_k(const float* __restrict__ XL, const float* __restrict__ XR,
                            const float* __restrict__ att, const int* __restrict__ srcs,
                            const int* __restrict__ dsts, float* __restrict__ score) {
    int lane = threadIdx.x & 31;
    int warp = (blockIdx.x * blockDim.x + threadIdx.x) >> 5;
    int nwarps = (gridDim.x * blockDim.x) >> 5;
    float a[16];
#pragma unroll
    for (int k = 0; k < 16; k++) a[k] = __ldg(&att[lane + 32 * k]);
    for (int e = warp; e < EE; e += nwarps) {
        int s = srcs[e], d = dsts[e];
        const float* xl = &XL[(size_t)s * HD];
        const float* xr = &XR[(size_t)d * HD];
        float p[4] = {0.f, 0.f, 0.f, 0.f};
#pragma unroll
        for (int k = 0; k < 16; k++) {
            float z = __ldg(&xl[lane + 32 * k]) + __ldg(&xr[lane + 32 * k]);
            z = z > 0.0f ? z : 0.2f * z;
            p[k >> 2] += z * a[k];
        }
#pragma unroll
        for (int h = 0; h < 4; h++) {
#pragma unroll
            for (int off = 16; off > 0; off >>= 1)
                p[h] += __shfl_down_sync(0xffffffffu, p[h], off);
        }
        if (lane == 0) {
            score[e * 4 + 0] = p[0];
            score[e * 4 + 1] = p[1];
            score[e * 4 + 2] = p[2];
            score[e * 4 + 3] = p[3];
        }
    }
}

// ---------------- segment softmax over dst (scores -> alpha, in place) -------------
// One thread per (dst, head). Caches exp values for segments up to 16 edges
// (mean degree is 4); falls back to a recompute pass for longer segments.
__global__ void seg_softmax_k(float* __restrict__ sc, const int* __restrict__ indptr) {
    int idx = blockIdx.x * blockDim.x + threadIdx.x;
    if (idx >= NN * HH) return;
    int d = idx >> 2, h = idx & 3;
    int e0 = indptr[d], e1 = indptr[d + 1];
    int len = e1 - e0;
    if (len <= 0) return;
    float m = -INFINITY;
    for (int e = e0; e < e1; e++) m = fmaxf(m, sc[e * 4 + h]);
    if (len <= 16) {
        float ev[16];
        float s = 0.0f;
        for (int i = 0; i < len; i++) {
            ev[i] = expf(sc[(e0 + i) * 4 + h] - m);
            s += ev[i];
        }
        float inv = 1.0f / (s + 1e-16f);
        for (int i = 0; i < len; i++) sc[(e0 + i) * 4 + h] = ev[i] * inv;
    } else {
        float s = 0.0f;
        for (int e = e0; e < e1; e++) s += expf(sc[e * 4 + h] - m);
        float inv = 1.0f / (s + 1e-16f);
        for (int e = e0; e < e1; e++) sc[e * 4 + h] = expf(sc[e * 4 + h] - m) * inv;
    }
}

// ---------------- GATv2 aggregate: one warp per dst node -------------------------
__global__ void gat_aggr_k(const float* __restrict__ XL, const float* __restrict__ alpha,
                           const int* __restrict__ indptr, const int* __restrict__ srcs,
                           const float* __restrict__ bias, float* __restrict__ out) {
    int lane = threadIdx.x & 31;
    int warp = (blockIdx.x * blockDim.x + threadIdx.x) >> 5;
    int nwarps = (gridDim.x * blockDim.x) >> 5;
    for (int d = warp; d < NN; d += nwarps) {
        float acc[16];
#pragma unroll
        for (int k = 0; k < 16; k++) acc[k] = 0.0f;
        int e0 = indptr[d], e1 = indptr[d + 1];
        for (int e = e0; e < e1; e++) {
            int s = srcs[e];
            float4 al = *(const float4*)&alpha[e * 4];  // broadcast across lanes
            float alh[4] = {al.x, al.y, al.z, al.w};
            const float* xl = &XL[(size_t)s * HD];
#pragma unroll
            for (int k = 0; k < 16; k++)
                acc[k] += __ldg(&xl[lane + 32 * k]) * alh[k >> 2];
        }
#pragma unroll
        for (int dc = 0; dc < 4; dc++) {
            int dd = lane + 32 * dc;
            float v = 0.25f * (acc[dc] + acc[dc + 4] + acc[dc + 8] + acc[dc + 12]);
            out[(size_t)d * DD + dd] = v + __ldg(&bias[dd]);
        }
    }
}

// ---------------- CGConv aggregate: one warp per dst node (out += sum + residual) ---
__global__ void cg_aggr_k(const float* __restrict__ Fd, const float* __restrict__ Fs,
                          const float* __restrict__ Sd, const float* __restrict__ Ss,
                          const float* __restrict__ xdst, const int* __restrict__ indptr,
                          const int* __restrict__ srcs, float* __restrict__ out) {
    int lane = threadIdx.x & 31;
    int warp = (blockIdx.x * blockDim.x + threadIdx.x) >> 5;
    int nwarps = (gridDim.x * blockDim.x) >> 5;
    for (int d = warp; d < NN; d += nwarps) {
        float fd[4], sd[4], acc[4];
#pragma unroll
        for (int c = 0; c < 4; c++) {
            int dd = lane + 32 * c;
            fd[c] = Fd[(size_t)d * DD + dd];
            sd[c] = Sd[(size_t)d * DD + dd];
            acc[c] = out[(size_t)d * DD + dd] + xdst[(size_t)d * DD + dd];
        }
        int e0 = indptr[d], e1 = indptr[d + 1];
        for (int e = e0; e < e1; e++) {
            int s = srcs[e];
#pragma unroll
            for (int c = 0; c < 4; c++) {
                int dd = lane + 32 * c;
                float f = fd[c] + __ldg(&Fs[(size_t)s * DD + dd]);
                float g = sd[c] + __ldg(&Ss[(size_t)s * DD + dd]);
                acc[c] += sigmoidf_(f) * softplusf_(g);
            }
        }
#pragma unroll
        for (int c = 0; c < 4; c++)
            out[(size_t)d * DD + lane + 32 * c] = acc[c];
    }
}

// ---------------- host orchestration ----------------
static void sgemm(const float* A, const float* B, const float* bias, float* C,
                  int M, int Ncols) {
    dim3 grid(Ncols / 128, (M + 127) / 128);
    sgemm128<<<grid, 256>>>(A, B, bias, C, M, Ncols);
}

extern "C" void kernel_launch(void* const* d_in, const int* in_sizes, int n_in,
                              void* d_out, int out_size) {
    (void)in_sizes; (void)n_in; (void)out_size;

    const float* in_xmy  = (const float*)d_in[0];
    const float* in_xopp = (const float*)d_in[1];
    const float* gb_Wl  = (const float*)d_in[2];
    const float* gb_Wr  = (const float*)d_in[3];
    const float* gb_att = (const float*)d_in[4];
    const float* gb_b   = (const float*)d_in[5];
    const float* gr_Wl  = (const float*)d_in[6];
    const float* gr_Wr  = (const float*)d_in[7];
    const float* gr_att = (const float*)d_in[8];
    const float* gr_b   = (const float*)d_in[9];
    const float* cl_Wf  = (const float*)d_in[10];
    const float* cl_bf  = (const float*)d_in[11];
    const float* cl_Ws  = (const float*)d_in[12];
    const float* cl_bs  = (const float*)d_in[13];
    const float* cr_Wf  = (const float*)d_in[14];
    const float* cr_bf  = (const float*)d_in[15];
    const float* cr_Ws  = (const float*)d_in[16];
    const float* cr_bs  = (const float*)d_in[17];
    const float* nw_W   = (const float*)d_in[18];
    const float* nw_b   = (const float*)d_in[19];

    // relations: 0=beats(dst=opp), 1=loses(dst=opp), 2=rev_beats(dst=my), 3=rev_loses(dst=my)
    const int* ei[4] = {(const int*)d_in[20], (const int*)d_in[21],
                        (const int*)d_in[22], (const int*)d_in[23]};

    float *XL, *XR, *Fd, *Fs, *Sd, *Ss, *alpha, *tmp_my, *tmp_opp, *xmy_b, *xopp_b;
    int *indptr, *cnt, *cursor, *srcs, *dsts;
    cudaGetSymbolAddress((void**)&XL, g_XL);
    cudaGetSymbolAddress((void**)&XR, g_XR);
    cudaGetSymbolAddress((void**)&Fd, g_Fd);
    cudaGetSymbolAddress((void**)&Fs, g_Fs);
    cudaGetSymbolAddress((void**)&Sd, g_Sd);
    cudaGetSymbolAddress((void**)&Ss, g_Ss);
    cudaGetSymbolAddress((void**)&alpha, g_alpha);
    cudaGetSymbolAddress((void**)&tmp_my, g_tmp_my);
    cudaGetSymbolAddress((void**)&tmp_opp, g_tmp_opp);
    cudaGetSymbolAddress((void**)&xmy_b, g_xmy);
    cudaGetSymbolAddress((void**)&xopp_b, g_xopp);
    cudaGetSymbolAddress((void**)&indptr, g_indptr);
    cudaGetSymbolAddress((void**)&cnt, g_cnt);
    cudaGetSymbolAddress((void**)&cursor, g_cursor);
    cudaGetSymbolAddress((void**)&srcs, g_srcs);
    cudaGetSymbolAddress((void**)&dsts, g_dsts);

    const int EB = (EE + 255) / 256;
    // ---- CSR build (4 relations) ----
    for (int r = 0; r < 4; r++) {
        int* cntR = cnt + r * NN;
        int* ipR  = indptr + r * (NN + 1);
        int* curR = cursor + r * NN;
        cudaMemsetAsync(cntR, 0, NN * sizeof(int), 0);
        count_k<<<EB, 256>>>(ei[r] + EE, cntR);
        exscan_k<<<1, 1024>>>(cntR, ipR);
        cudaMemcpyAsync(curR, ipR, NN * sizeof(int), cudaMemcpyDeviceToDevice, 0);
        scatter_k<<<EB, 256>>>(ei[r], ei[r] + EE, curR, srcs + r * EE, dsts + r * EE);
    }

    const int AGG_BLOCKS = 1184;   // 148 SMs * 8
    const float* xmy = in_xmy;
    const float* xopp = in_xopp;

    for (int l = 0; l < 2; l++) {
        const size_t wlOff = (size_t)l * 128 * 512;
        const size_t atOff = (size_t)l * 512;
        const size_t bOff  = (size_t)l * 128;
        const size_t cgOff = (size_t)l * 256 * 128;
        const size_t nwOff = (size_t)l * 128 * 128;
        float* out_my  = (l == 0) ? xmy_b  : ((float*)d_out);
        float* out_opp = (l == 0) ? xopp_b : ((float*)d_out + (size_t)NN * DD);

        // ======== opp_new: GATv2(beats: my->opp) + CGConv(loses: my->opp) ========
        sgemm(xmy,  gb_Wl + wlOff, nullptr, XL, NN, 512);
        sgemm(xopp, gb_Wr + wlOff, nullptr, XR, NN, 512);
        gat_score_k<<<AGG_BLOCKS, 256>>>(XL, XR, gb_att + atOff, srcs + 0 * EE,
                                         dsts + 0 * EE, alpha);
        seg_softmax_k<<<(NN * HH + 255) / 256, 256>>>(alpha, indptr + 0 * (NN + 1));
        gat_aggr_k<<<AGG_BLOCKS, 256>>>(XL, alpha, indptr + 0 * (NN + 1), srcs + 0 * EE,
                                        gb_b + bOff, tmp_opp);
        // CGConv loses: z = [x_opp(dst), x_my(src)]
        sgemm(xopp, cl_Wf + cgOff,             cl_bf + bOff, Fd, NN, 128);
        sgemm(xmy,  cl_Wf + cgOff + 128 * 128, nullptr,      Fs, NN, 128);
        sgemm(xopp, cl_Ws + cgOff,             cl_bs + bOff, Sd, NN, 128);
        sgemm(xmy,  cl_Ws + cgOff + 128 * 128, nullptr,      Ss, NN, 128);
        cg_aggr_k<<<AGG_BLOCKS, 256>>>(Fd, Fs, Sd, Ss, xopp, indptr + 1 * (NN + 1),
                                       srcs + 1 * EE, tmp_opp);

        // ======== my_new: CGConv(rev_beats: opp->my) + GATv2(rev_loses: opp->my) ====
        sgemm(xopp, gr_Wl + wlOff, nullptr, XL, NN, 512);
        sgemm(xmy,  gr_Wr + wlOff, nullptr, XR, NN, 512);
        gat_score_k<<<AGG_BLOCKS, 256>>>(XL, XR, gr_att + atOff, srcs + 3 * EE,
                                         dsts + 3 * EE, alpha);
        seg_softmax_k<<<(NN * HH + 255) / 256, 256>>>(alpha, indptr + 3 * (NN + 1));
        gat_aggr_k<<<AGG_BLOCKS, 256>>>(XL, alpha, indptr + 3 * (NN + 1), srcs + 3 * EE,
                                        gr_b + bOff, tmp_my);
        // CGConv rev_beats: z = [x_my(dst), x_opp(src)]
        sgemm(xmy,  cr_Wf + cgOff,             cr_bf + bOff, Fd, NN, 128);
        sgemm(xopp, cr_Wf + cgOff + 128 * 128, nullptr,      Fs, NN, 128);
        sgemm(xmy,  cr_Ws + cgOff,             cr_bs + bOff, Sd, NN, 128);
        sgemm(xopp, cr_Ws + cgOff + 128 * 128, nullptr,      Ss, NN, 128);
        cg_aggr_k<<<AGG_BLOCKS, 256>>>(Fd, Fs, Sd, Ss, xmy, indptr + 2 * (NN + 1),
                                       srcs + 2 * EE, tmp_my);

        // ======== shared nodewise Linear ========
        sgemm(tmp_my,  nw_W + nwOff, nw_b + bOff, out_my,  NN, 128);
        sgemm(tmp_opp, nw_W + nwOff, nw_b + bOff, out_opp, NN, 128);

        xmy = out_my;
        xopp = out_opp;
    }
}

// round 8
// speedup vs baseline: 1.1024x; 1.1024x over previous
#include <cuda_runtime.h>
#include <math.h>

#define NN 20000
#define EE 80000
#define DD 128
#define HH 4
#define HD 512          // H*D

// ---------------- scratch (device globals; no allocations allowed) ----------------
__device__ float g_XL[NN * HD];
__device__ float g_XR[NN * HD];
__device__ float g_Fd[NN * DD];
__device__ float g_Fs[NN * DD];
__device__ float g_Sd[NN * DD];
__device__ float g_Ss[NN * DD];
__device__ float g_alpha[EE * HH];
__device__ float g_tmp[2 * NN * DD];    // [tmp_my | tmp_opp] contiguous
__device__ float g_xbuf[2 * NN * DD];   // layer-0 output [my | opp]
__device__ int   g_indptr[4 * (NN + 1)];
__device__ int   g_cnt[4 * NN];
__device__ int   g_cursor[4 * NN];
__device__ int   g_srcs[4 * EE];
__device__ int   g_dsts[4 * EE];

// ---------------- helpers ----------------
__device__ __forceinline__ float sigmoidf_(float x) { return 1.0f / (1.0f + expf(-x)); }
__device__ __forceinline__ float softplusf_(float x) {
    return fmaxf(x, 0.0f) + log1pf(expf(-fabsf(x)));
}

__device__ __forceinline__ unsigned long long pack2(float x, float y) {
    unsigned long long r;
    asm("mov.b64 %0, {%1, %2};" : "=l"(r) : "f"(x), "f"(y));
    return r;
}
__device__ __forceinline__ void unpack2(unsigned long long v, float& x, float& y) {
    asm("mov.b64 {%0, %1}, %2;" : "=f"(x), "=f"(y) : "l"(v));
}
__device__ __forceinline__ void fma2(unsigned long long& d, unsigned long long a,
                                     unsigned long long b) {
    asm("fma.rn.f32x2 %0, %1, %2, %0;" : "+l"(d) : "l"(a), "l"(b));
}

// ---------------- CSR build (4 relations, 4 launches total) ----------------
__global__ void zero_k(int* __restrict__ cnt) {
    int i = blockIdx.x * blockDim.x + threadIdx.x;
    if (i < 4 * NN) cnt[i] = 0;
}

__global__ void count_all_k(const int* __restrict__ e0, const int* __restrict__ e1,
                            const int* __restrict__ e2, const int* __restrict__ e3,
                            int* __restrict__ cnt) {
    int i = blockIdx.x * blockDim.x + threadIdx.x;
    if (i >= 4 * EE) return;
    int r = i / EE, e = i - r * EE;
    const int* dst = (r == 0) ? e0 : (r == 1) ? e1 : (r == 2) ? e2 : e3;
    atomicAdd(&cnt[r * NN + dst[EE + e]], 1);
}

// one block per relation; also writes cursor[i] = exclusive prefix (= indptr[i])
__global__ void exscan4_k(const int* __restrict__ cnt, int* __restrict__ indptr,
                          int* __restrict__ cursor) {
    __shared__ int buf[1024];
    __shared__ int carry;
    int r = blockIdx.x;
    const int* c = cnt + r * NN;
    int* ip = indptr + r * (NN + 1);
    int* cur = cursor + r * NN;
    int t = threadIdx.x;
    if (t == 0) { carry = 0; ip[0] = 0; }
    __syncthreads();
    for (int base = 0; base < NN; base += 1024) {
        int i = base + t;
        int v = (i < NN) ? c[i] : 0;
        buf[t] = v;
        __syncthreads();
        for (int off = 1; off < 1024; off <<= 1) {
            int tv = (t >= off) ? buf[t - off] : 0;
            __syncthreads();
            buf[t] += tv;
            __syncthreads();
        }
        if (i < NN) {
            ip[i + 1] = carry + buf[t];
            cur[i] = carry + buf[t] - v;
        }
        __syncthreads();
        if (t == 0) carry += buf[1023];
        __syncthreads();
    }
}

__global__ void scatter_all_k(const int* __restrict__ e0, const int* __restrict__ e1,
                              const int* __restrict__ e2, const int* __restrict__ e3,
                              int* __restrict__ cursor, int* __restrict__ srcs,
                              int* __restrict__ dsts) {
    int i = blockIdx.x * blockDim.x + threadIdx.x;
    if (i >= 4 * EE) return;
    int r = i / EE, e = i - r * EE;
    const int* ei = (r == 0) ? e0 : (r == 1) ? e1 : (r == 2) ? e2 : e3;
    int d = ei[EE + e];
    int p = atomicAdd(&cursor[r * NN + d], 1);
    srcs[r * EE + p] = ei[e];
    dsts[r * EE + p] = d;
}

// ---------------- fp32 SGEMM with fma.rn.f32x2: C[M,Ncols]=A[M,128]@B[128,Ncols]+bias ---
// Tile 128x128, BK=16, 256 threads, 8x8 per thread (4 packed col-pairs).
__global__ __launch_bounds__(256) void sgemm128(const float* __restrict__ A,
                                                const float* __restrict__ B,
                                                const float* __restrict__ bias,
                                                float* __restrict__ C,
                                                int M, int Ncols) {
    __shared__ float As[16][128];
    __shared__ float Bs[16][128];
    const int brow = blockIdx.y * 128;
    const int bcol = blockIdx.x * 128;
    const int tid = threadIdx.x;
    const int tx = tid & 15;
    const int ty = tid >> 4;

    unsigned long long acc[8][4];
#pragma unroll
    for (int i = 0; i < 8; i++)
#pragma unroll
        for (int j = 0; j < 4; j++) acc[i][j] = 0ULL;

    for (int k0 = 0; k0 < 128; k0 += 16) {
#pragma unroll
        for (int i = 0; i < 2; i++) {
            int idx = tid + i * 256;
            int r = idx >> 2;
            int c4 = (idx & 3) * 4;
            float4 v = make_float4(0.f, 0.f, 0.f, 0.f);
            int gr = brow + r;
            if (gr < M) v = *(const float4*)&A[(size_t)gr * 128 + k0 + c4];
            As[c4 + 0][r] = v.x;
            As[c4 + 1][r] = v.y;
            As[c4 + 2][r] = v.z;
            As[c4 + 3][r] = v.w;
        }
#pragma unroll
        for (int i = 0; i < 2; i++) {
            int idx = tid + i * 256;
            int r = idx >> 5;
            int c4 = (idx & 31) * 4;
            float4 v = *(const float4*)&B[(size_t)(k0 + r) * Ncols + bcol + c4];
            *(float4*)&Bs[r][c4] = v;
        }
        __syncthreads();
#pragma unroll
        for (int kk = 0; kk < 16; kk++) {
            float4 a0 = *(const float4*)&As[kk][ty * 8];
            float4 a1 = *(const float4*)&As[kk][ty * 8 + 4];
            float4 b0 = *(const float4*)&Bs[kk][tx * 8];
            float4 b1 = *(const float4*)&Bs[kk][tx * 8 + 4];
            unsigned long long bb[4];
            bb[0] = pack2(b0.x, b0.y);
            bb[1] = pack2(b0.z, b0.w);
            bb[2] = pack2(b1.x, b1.y);
            bb[3] = pack2(b1.z, b1.w);
            float a[8] = {a0.x, a0.y, a0.z, a0.w, a1.x, a1.y, a1.z, a1.w};
#pragma unroll
            for (int i = 0; i < 8; i++) {
                unsigned long long aa = pack2(a[i], a[i]);
#pragma unroll
                for (int j = 0; j < 4; j++) fma2(acc[i][j], aa, bb[j]);
            }
        }
        __syncthreads();
    }

#pragma unroll
    for (int i = 0; i < 8; i++) {
        int gr = brow + ty * 8 + i;
        if (gr < M) {
            float out[8];
#pragma unroll
            for (int j = 0; j < 4; j++) unpack2(acc[i][j], out[2 * j], out[2 * j + 1]);
#pragma unroll
            for (int j = 0; j < 8; j++) {
                int gc = bcol + tx * 8 + j;
                float v = out[j];
                if (bias) v += bias[gc];
                C[(size_t)gr * Ncols + gc] = v;
            }
        }
    }
}

// ---------------- dual-B SGEMM (Ncols=128 fixed): shares the A tile across two B's ----
// C1 = A@B1 + b1, C2 = A@B2 + b2.  Tile 128x128, BK=16, 256 threads.
__global__ __launch_bounds__(256) void sgemm128_dual(const float* __restrict__ A,
                                                     const float* __restrict__ B1,
                                                     const float* __restrict__ b1v,
                                                     float* __restrict__ C1,
                                                     const float* __restrict__ B2,
                                                     const float* __restrict__ b2v,
                                                     float* __restrict__ C2,
                                                     int M) {
    __shared__ float As[16][128];
    __shared__ float B1s[16][128];
    __shared__ float B2s[16][128];
    const int brow = blockIdx.y * 128;
    const int tid = threadIdx.x;
    const int tx = tid & 15;
    const int ty = tid >> 4;

    unsigned long long acc1[8][4], acc2[8][4];
#pragma unroll
    for (int i = 0; i < 8; i++)
#pragma unroll
        for (int j = 0; j < 4; j++) { acc1[i][j] = 0ULL; acc2[i][j] = 0ULL; }

    for (int k0 = 0; k0 < 128; k0 += 16) {
#pragma unroll
        for (int i = 0; i < 2; i++) {
            int idx = tid + i * 256;
            int r = idx >> 2;
            int c4 = (idx & 3) * 4;
            float4 v = make_float4(0.f, 0.f, 0.f, 0.f);
            int gr = brow + r;
            if (gr < M) v = *(const float4*)&A[(size_t)gr * 128 + k0 + c4];
            As[c4 + 0][r] = v.x;
            As[c4 + 1][r] = v.y;
            As[c4 + 2][r] = v.z;
            As[c4 + 3][r] = v.w;
        }
#pragma unroll
        for (int i = 0; i < 2; i++) {
            int idx = tid + i * 256;
            int r = idx >> 5;
            int c4 = (idx & 31) * 4;
            *(float4*)&B1s[r][c4] = *(const float4*)&B1[(size_t)(k0 + r) * 128 + c4];
            *(float4*)&B2s[r][c4] = *(const float4*)&B2[(size_t)(k0 + r) * 128 + c4];
        }
        __syncthreads();
#pragma unroll
        for (int kk = 0; kk < 16; kk++) {
            float4 a0 = *(const float4*)&As[kk][ty * 8];
            float4 a1 = *(const float4*)&As[kk][ty * 8 + 4];
            unsigned long long aa[8];
            aa[0] = pack2(a0.x, a0.x); aa[1] = pack2(a0.y, a0.y);
            aa[2] = pack2(a0.z, a0.z); aa[3] = pack2(a0.w, a0.w);
            aa[4] = pack2(a1.x, a1.x); aa[5] = pack2(a1.y, a1.y);
            aa[6] = pack2(a1.z, a1.z); aa[7] = pack2(a1.w, a1.w);
            {
                float4 b0 = *(const float4*)&B1s[kk][tx * 8];
                float4 b1 = *(const float4*)&B1s[kk][tx * 8 + 4];
                unsigned long long bb[4];
                bb[0] = pack2(b0.x, b0.y);
                bb[1] = pack2(b0.z, b0.w);
                bb[2] = pack2(b1.x, b1.y);
                bb[3] = pack2(b1.z, b1.w);
#pragma unroll
                for (int i = 0; i < 8; i++)
#pragma unroll
                    for (int j = 0; j < 4; j++) fma2(acc1[i][j], aa[i], bb[j]);
            }
            {
                float4 b0 = *(const float4*)&B2s[kk][tx * 8];
                float4 b1 = *(const float4*)&B2s[kk][tx * 8 + 4];
                unsigned long long bb[4];
                bb[0] = pack2(b0.x, b0.y);
                bb[1] = pack2(b0.z, b0.w);
                bb[2] = pack2(b1.x, b1.y);
                bb[3] = pack2(b1.z, b1.w);
#pragma unroll
                for (int i = 0; i < 8; i++)
#pragma unroll
                    for (int j = 0; j < 4; j++) fma2(acc2[i][j], aa[i], bb[j]);
            }
        }
        __syncthreads();
    }

#pragma unroll
    for (int i = 0; i < 8; i++) {
        int gr = brow + ty * 8 + i;
        if (gr < M) {
            float o1[8], o2[8];
#pragma unroll
            for (int j = 0; j < 4; j++) {
                unpack2(acc1[i][j], o1[2 * j], o1[2 * j + 1]);
                unpack2(acc2[i][j], o2[2 * j], o2[2 * j + 1]);
            }
#pragma unroll
            for (int j = 0; j < 8; j++) {
                int gc = tx * 8 + j;
                float v1 = o1[j], v2 = o2[j];
                if (b1v) v1 += b1v[gc];
                if (b2v) v2 += b2v[gc];
                C1[(size_t)gr * 128 + gc] = v1;
                C2[(size_t)gr * 128 + gc] = v2;
            }
        }
    }
}

// ---------------- GATv2 edge score: one warp per edge (grid-stride) ----------------
__global__ void gat_score_k(const float* __restrict__ XL, const float* __restrict__ XR,
                            const float* __restrict__ att, const int* __restrict__ srcs,
                            const int* __restrict__ dsts, float* __restrict__ score) {
    int lane = threadIdx.x & 31;
    int warp = (blockIdx.x * blockDim.x + threadIdx.x) >> 5;
    int nwarps = (gridDim.x * blockDim.x) >> 5;
    float a[16];
#pragma unroll
    for (int k = 0; k < 16; k++) a[k] = __ldg(&att[lane + 32 * k]);
    for (int e = warp; e < EE; e += nwarps) {
        int s = srcs[e], d = dsts[e];
        const float* xl = &XL[(size_t)s * HD];
        const float* xr = &XR[(size_t)d * HD];
        float p[4] = {0.f, 0.f, 0.f, 0.f};
#pragma unroll
        for (int k = 0; k < 16; k++) {
            float z = __ldg(&xl[lane + 32 * k]) + __ldg(&xr[lane + 32 * k]);
            z = z > 0.0f ? z : 0.2f * z;
            p[k >> 2] += z * a[k];
        }
#pragma unroll
        for (int h = 0; h < 4; h++) {
#pragma unroll
            for (int off = 16; off > 0; off >>= 1)
                p[h] += __shfl_down_sync(0xffffffffu, p[h], off);
        }
        if (lane == 0) {
            score[e * 4 + 0] = p[0];
            score[e * 4 + 1] = p[1];
            score[e * 4 + 2] = p[2];
            score[e * 4 + 3] = p[3];
        }
    }
}

// ---------------- segment softmax over dst (scores -> alpha, in place) -------------
__global__ void seg_softmax_k(float* __restrict__ sc, const int* __restrict__ indptr) {
    int idx = blockIdx.x * blockDim.x + threadIdx.x;
    if (idx >= NN * HH) return;
    int d = idx >> 2, h = idx & 3;
    int e0 = indptr[d], e1 = indptr[d + 1];
    int len = e1 - e0;
    if (len <= 0) return;
    float m = -INFINITY;
    for (int e = e0; e < e1; e++) m = fmaxf(m, sc[e * 4 + h]);
    if (len <= 16) {
        float ev[16];
        float s = 0.0f;
        for (int i = 0; i < len; i++) {
            ev[i] = expf(sc[(e0 + i) * 4 + h] - m);
            s += ev[i];
        }
        float inv = 1.0f / (s + 1e-16f);
        for (int i = 0; i < len; i++) sc[(e0 + i) * 4 + h] = ev[i] * inv;
    } else {
        float s = 0.0f;
        for (int e = e0; e < e1; e++) s += expf(sc[e * 4 + h] - m);
        float inv = 1.0f / (s + 1e-16f);
        for (int e = e0; e < e1; e++) sc[e * 4 + h] = expf(sc[e * 4 + h] - m) * inv;
    }
}

// ---------------- GATv2 aggregate: one warp per dst node -------------------------
__global__ void gat_aggr_k(const float* __restrict__ XL, const float* __restrict__ alpha,
                           const int* __restrict__ indptr, const int* __restrict__ srcs,
                           const float* __restrict__ bias, float* __restrict__ out) {
    int lane = threadIdx.x & 31;
    int warp = (blockIdx.x * blockDim.x + threadIdx.x) >> 5;
    int nwarps = (gridDim.x * blockDim.x) >> 5;
    for (int d = warp; d < NN; d += nwarps) {
        float acc[16];
#pragma unroll
        for (int k = 0; k < 16; k++) acc[k] = 0.0f;
        int e0 = indptr[d], e1 = indptr[d + 1];
        for (int e = e0; e < e1; e++) {
            int s = srcs[e];
            float4 al = *(const float4*)&alpha[e * 4];
            float alh[4] = {al.x, al.y, al.z, al.w};
            const float* xl = &XL[(size_t)s * HD];
#pragma unroll
            for (int k = 0; k < 16; k++)
                acc[k] += __ldg(&xl[lane + 32 * k]) * alh[k >> 2];
        }
#pragma unroll
        for (int dc = 0; dc < 4; dc++) {
            int dd = lane + 32 * dc;
            float v = 0.25f * (acc[dc] + acc[dc + 4] + acc[dc + 8] + acc[dc + 12]);
            out[(size_t)d * DD + dd] = v + __ldg(&bias[dd]);
        }
    }
}

// ---------------- CGConv aggregate: one warp per dst node (out += sum + residual) ---
__global__ void cg_aggr_k(const float* __restrict__ Fd, const float* __restrict__ Fs,
                          const float* __restrict__ Sd, const float* __restrict__ Ss,
                          const float* __restrict__ xdst, const int* __restrict__ indptr,
                          const int* __restrict__ srcs, float* __restrict__ out) {
    int lane = threadIdx.x & 31;
    int warp = (blockIdx.x * blockDim.x + threadIdx.x) >> 5;
    int nwarps = (gridDim.x * blockDim.x) >> 5;
    for (int d = warp; d < NN; d += nwarps) {
        float fd[4], sd[4], acc[4];
#pragma unroll
        for (int c = 0; c < 4; c++) {
            int dd = lane + 32 * c;
            fd[c] = Fd[(size_t)d * DD + dd];
            sd[c] = Sd[(size_t)d * DD + dd];
            acc[c] = out[(size_t)d * DD + dd] + xdst[(size_t)d * DD + dd];
        }
        int e0 = indptr[d], e1 = indptr[d + 1];
        for (int e = e0; e < e1; e++) {
            int s = srcs[e];
#pragma unroll
            for (int c = 0; c < 4; c++) {
                int dd = lane + 32 * c;
                float f = fd[c] + __ldg(&Fs[(size_t)s * DD + dd]);
                float g = sd[c] + __ldg(&Ss[(size_t)s * DD + dd]);
                acc[c] += sigmoidf_(f) * softplusf_(g);
            }
        }
#pragma unroll
        for (int c = 0; c < 4; c++)
            out[(size_t)d * DD + lane + 32 * c] = acc[c];
    }
}

// ---------------- host orchestration ----------------
static void sgemm(const float* A, const float* B, const float* bias, float* C,
                  int M, int Ncols) {
    dim3 grid(Ncols / 128, (M + 127) / 128);
    sgemm128<<<grid, 256>>>(A, B, bias, C, M, Ncols);
}

static void sgemm_dual(const float* A, const float* B1, const float* b1, float* C1,
                       const float* B2, const float* b2, float* C2, int M) {
    dim3 grid(1, (M + 127) / 128);
    sgemm128_dual<<<grid, 256>>>(A, B1, b1, C1, B2, b2, C2, M);
}

extern "C" void kernel_launch(void* const* d_in, const int* in_sizes, int n_in,
                              void* d_out, int out_size) {
    (void)in_sizes; (void)n_in; (void)out_size;

    const float* in_xmy  = (const float*)d_in[0];
    const float* in_xopp = (const float*)d_in[1];
    const float* gb_Wl  = (const float*)d_in[2];
    const float* gb_Wr  = (const float*)d_in[3];
    const float* gb_att = (const float*)d_in[4];
    const float* gb_b   = (const float*)d_in[5];
    const float* gr_Wl  = (const float*)d_in[6];
    const float* gr_Wr  = (const float*)d_in[7];
    const float* gr_att = (const float*)d_in[8];
    const float* gr_b   = (const float*)d_in[9];
    const float* cl_Wf  = (const float*)d_in[10];
    const float* cl_bf  = (const float*)d_in[11];
    const float* cl_Ws  = (const float*)d_in[12];
    const float* cl_bs  = (const float*)d_in[13];
    const float* cr_Wf  = (const float*)d_in[14];
    const float* cr_bf  = (const float*)d_in[15];
    const float* cr_Ws  = (const float*)d_in[16];
    const float* cr_bs  = (const float*)d_in[17];
    const float* nw_W   = (const float*)d_in[18];
    const float* nw_b   = (const float*)d_in[19];

    // relations: 0=beats(dst=opp), 1=loses(dst=opp), 2=rev_beats(dst=my), 3=rev_loses(dst=my)
    const int* e0 = (const int*)d_in[20];
    const int* e1 = (const int*)d_in[21];
    const int* e2 = (const int*)d_in[22];
    const int* e3 = (const int*)d_in[23];

    float *XL, *XR, *Fd, *Fs, *Sd, *Ss, *alpha, *tmp, *xbuf;
    int *indptr, *cnt, *cursor, *srcs, *dsts;
    cudaGetSymbolAddress((void**)&XL, g_XL);
    cudaGetSymbolAddress((void**)&XR, g_XR);
    cudaGetSymbolAddress((void**)&Fd, g_Fd);
    cudaGetSymbolAddress((void**)&Fs, g_Fs);
    cudaGetSymbolAddress((void**)&Sd, g_Sd);
    cudaGetSymbolAddress((void**)&Ss, g_Ss);
    cudaGetSymbolAddress((void**)&alpha, g_alpha);
    cudaGetSymbolAddress((void**)&tmp, g_tmp);
    cudaGetSymbolAddress((void**)&xbuf, g_xbuf);
    cudaGetSymbolAddress((void**)&indptr, g_indptr);
    cudaGetSymbolAddress((void**)&cnt, g_cnt);
    cudaGetSymbolAddress((void**)&cursor, g_cursor);
    cudaGetSymbolAddress((void**)&srcs, g_srcs);
    cudaGetSymbolAddress((void**)&dsts, g_dsts);

    float* tmp_my  = tmp;
    float* tmp_opp = tmp + (size_t)NN * DD;

    // ---- CSR build: 4 launches (launch idx 0..3) ----
    zero_k<<<(4 * NN + 255) / 256, 256>>>(cnt);
    count_all_k<<<(4 * EE + 255) / 256, 256>>>(e0, e1, e2, e3, cnt);
    exscan4_k<<<4, 1024>>>(cnt, indptr, cursor);
    scatter_all_k<<<(4 * EE + 255) / 256, 256>>>(e0, e1, e2, e3, cursor, srcs, dsts);

    const int AGG_BLOCKS = 1184;   // 148 SMs * 8
    const float* xmy = in_xmy;
    const float* xopp = in_xopp;

    for (int l = 0; l < 2; l++) {
        const size_t wlOff = (size_t)l * 128 * 512;
        const size_t atOff = (size_t)l * 512;
        const size_t bOff  = (size_t)l * 128;
        const size_t cgOff = (size_t)l * 256 * 128;
        const size_t nwOff = (size_t)l * 128 * 128;
        float* outbuf = (l == 0) ? xbuf : (float*)d_out;   // [my | opp] contiguous

        // ======== opp_new: GATv2(beats: my->opp) + CGConv(loses: my->opp) ========
        sgemm(xmy,  gb_Wl + wlOff, nullptr, XL, NN, 512);   // launch idx 4 (l=0)
        sgemm(xopp, gb_Wr + wlOff, nullptr, XR, NN, 512);   // launch idx 5 -> ncu target
        gat_score_k<<<AGG_BLOCKS, 256>>>(XL, XR, gb_att + atOff, srcs + 0 * EE,
                                         dsts + 0 * EE, alpha);
        seg_softmax_k<<<(NN * HH + 255) / 256, 256>>>(alpha, indptr + 0 * (NN + 1));
        gat_aggr_k<<<AGG_BLOCKS, 256>>>(XL, alpha, indptr + 0 * (NN + 1), srcs + 0 * EE,
                                        gb_b + bOff, tmp_opp);
        // CGConv loses: z = [x_opp(dst), x_my(src)]
        sgemm_dual(xopp, cl_Wf + cgOff, cl_bf + bOff, Fd,
                         cl_Ws + cgOff, cl_bs + bOff, Sd, NN);
        sgemm_dual(xmy,  cl_Wf + cgOff + 128 * 128, nullptr, Fs,
                         cl_Ws + cgOff + 128 * 128, nullptr, Ss, NN);
        cg_aggr_k<<<AGG_BLOCKS, 256>>>(Fd, Fs, Sd, Ss, xopp, indptr + 1 * (NN + 1),
                                       srcs + 1 * EE, tmp_opp);

        // ======== my_new: CGConv(rev_beats: opp->my) + GATv2(rev_loses: opp->my) ====
        sgemm(xopp, gr_Wl + wlOff, nullptr, XL, NN, 512);
        sgemm(xmy,  gr_Wr + wlOff, nullptr, XR, NN, 512);
        gat_score_k<<<AGG_BLOCKS, 256>>>(XL, XR, gr_att + atOff, srcs + 3 * EE,
                                         dsts + 3 * EE, alpha);
        seg_softmax_k<<<(NN * HH + 255) / 256, 256>>>(alpha, indptr + 3 * (NN + 1));
        gat_aggr_k<<<AGG_BLOCKS, 256>>>(XL, alpha, indptr + 3 * (NN + 1), srcs + 3 * EE,
                                        gr_b + bOff, tmp_my);
        // CGConv rev_beats: z = [x_my(dst), x_opp(src)]
        sgemm_dual(xmy,  cr_Wf + cgOff, cr_bf + bOff, Fd,
                         cr_Ws + cgOff, cr_bs + bOff, Sd, NN);
        sgemm_dual(xopp, cr_Wf + cgOff + 128 * 128, nullptr, Fs,
                         cr_Ws + cgOff + 128 * 128, nullptr, Ss, NN);
        cg_aggr_k<<<AGG_BLOCKS, 256>>>(Fd, Fs, Sd, Ss, xmy, indptr + 2 * (NN + 1),
                                       srcs + 2 * EE, tmp_my);

        // ======== shared nodewise Linear: both node types in ONE GEMM (M=2*NN) ====
        sgemm(tmp, nw_W + nwOff, nw_b + bOff, outbuf, 2 * NN, 128);

        xmy = outbuf;
        xopp = outbuf + (size_t)NN * DD;
    }
}